// round 1
// baseline (speedup 1.0000x reference)
#include <cuda_runtime.h>

#define B_ 8
#define T_ 4096
#define C_ 1024
#define H_ 128

// Scratch for Q,K,V projections: 3 * 8*4096*128 floats = 48 MB (static, allocation-free)
__device__ float g_Q[(size_t)B_ * T_ * H_];
__device__ float g_K[(size_t)B_ * T_ * H_];
__device__ float g_V[(size_t)B_ * T_ * H_];

// ---------------------------------------------------------------------------
// QKV projection: Y[row, h] = sum_c x[row, c] * W[h, c]
// M = 32768, N = 128, K = 1024. Tiles: BM=128, BN=128, BK=16, 8x8 microtile.
// grid = (256, 3): blockIdx.y selects Wq/Wk/Wv.
// ---------------------------------------------------------------------------
__global__ __launch_bounds__(256) void qkv_kernel(
    const float* __restrict__ x,
    const float* __restrict__ Wq,
    const float* __restrict__ Wk,
    const float* __restrict__ Wv) {
    __shared__ float Xs[16][128];   // [kk][row]  (K-major for broadcast reads)
    __shared__ float Ws[16][128];   // [kk][col]

    const float* W = (blockIdx.y == 0) ? Wq : (blockIdx.y == 1) ? Wk : Wv;
    float* Y       = (blockIdx.y == 0) ? g_Q : (blockIdx.y == 1) ? g_K : g_V;

    const int tid = threadIdx.x;
    const int tx = tid & 15;        // output col group
    const int ty = tid >> 4;        // output row group
    const int row0 = blockIdx.x * 128;

    float acc[8][8];
#pragma unroll
    for (int i = 0; i < 8; i++)
#pragma unroll
        for (int j = 0; j < 8; j++) acc[i][j] = 0.f;

    for (int k0 = 0; k0 < C_; k0 += 16) {
#pragma unroll
        for (int p = 0; p < 2; p++) {
            int e = (tid + p * 256) * 4;   // element index in 128x16 tile
            int r = e >> 4;                // tile row (0..127)
            int kk = e & 15;               // k offset (0,4,8,12)
            float4 vx = *(const float4*)&x[(size_t)(row0 + r) * C_ + k0 + kk];
            Xs[kk + 0][r] = vx.x; Xs[kk + 1][r] = vx.y;
            Xs[kk + 2][r] = vx.z; Xs[kk + 3][r] = vx.w;
            float4 vw = *(const float4*)&W[(size_t)r * C_ + k0 + kk];
            Ws[kk + 0][r] = vw.x; Ws[kk + 1][r] = vw.y;
            Ws[kk + 2][r] = vw.z; Ws[kk + 3][r] = vw.w;
        }
        __syncthreads();
#pragma unroll
        for (int kk = 0; kk < 16; kk++) {
            float a[8], b[8];
            *(float4*)&a[0] = *(const float4*)&Xs[kk][ty * 8];
            *(float4*)&a[4] = *(const float4*)&Xs[kk][ty * 8 + 4];
            *(float4*)&b[0] = *(const float4*)&Ws[kk][tx * 8];
            *(float4*)&b[4] = *(const float4*)&Ws[kk][tx * 8 + 4];
#pragma unroll
            for (int i = 0; i < 8; i++)
#pragma unroll
                for (int j = 0; j < 8; j++)
                    acc[i][j] = fmaf(a[i], b[j], acc[i][j]);
        }
        __syncthreads();
    }

#pragma unroll
    for (int i = 0; i < 8; i++) {
        size_t base = (size_t)(row0 + ty * 8 + i) * H_ + tx * 8;
        float4 o0 = make_float4(acc[i][0], acc[i][1], acc[i][2], acc[i][3]);
        float4 o1 = make_float4(acc[i][4], acc[i][5], acc[i][6], acc[i][7]);
        *(float4*)&Y[base] = o0;
        *(float4*)&Y[base + 4] = o1;
    }
}

// ---------------------------------------------------------------------------
// Flash attention, causal. BM=BN=64, HD=128. 256 threads = 16x16 grid.
// Thread (tx,ty) owns S rows {ty+16i}, S cols {tx+16jj} (strided, for
// conflict-free float4 smem reads) and O cols {tx*8..tx*8+7}.
// Scale folded into Q at load.
// ---------------------------------------------------------------------------
#define BM 64
#define BN 64
#define QSTR 132            // padded row stride (floats), keeps 16B alignment
#define PSTR 68
#define ATTN_SMEM_FLOATS (3 * BM * QSTR + BM * PSTR)   // 29696 floats = 116 KB

__global__ __launch_bounds__(256) void attn_kernel(float* __restrict__ out) {
    extern __shared__ float sm[];
    float* Qs = sm;                    // [64][132]
    float* Ks = Qs + BM * QSTR;        // [64][132]
    float* Vs = Ks + BN * QSTR;        // [64][132]
    float* Ps = Vs + BN * QSTR;        // [64][68]

    const int b  = blockIdx.y;
    const int qt = (int)gridDim.x - 1 - (int)blockIdx.x;  // big tiles first
    const int tid = threadIdx.x;
    const int tx = tid & 15;
    const int ty = tid >> 4;
    const float scale = 0.08838834764831843f;  // 1/sqrt(128)

    // Load + scale Q tile
    const float* Qg = g_Q + ((size_t)b * T_ + (size_t)qt * BM) * H_;
#pragma unroll
    for (int p = 0; p < 8; p++) {
        int e = (tid + p * 256) * 4;
        int r = e >> 7, h = e & 127;
        float4 v = *(const float4*)&Qg[(size_t)r * H_ + h];
        v.x *= scale; v.y *= scale; v.z *= scale; v.w *= scale;
        *(float4*)&Qs[r * QSTR + h] = v;
    }

    float m[4], l[4], o[4][8];
#pragma unroll
    for (int i = 0; i < 4; i++) {
        m[i] = -1e30f; l[i] = 0.f;
#pragma unroll
        for (int c = 0; c < 8; c++) o[i][c] = 0.f;
    }

    for (int j = 0; j <= qt; j++) {
        __syncthreads();   // protect Ks/Vs/Ps reuse from previous iteration
        const float* Kg = g_K + ((size_t)b * T_ + (size_t)j * BN) * H_;
        const float* Vg = g_V + ((size_t)b * T_ + (size_t)j * BN) * H_;
#pragma unroll
        for (int p = 0; p < 8; p++) {
            int e = (tid + p * 256) * 4;
            int r = e >> 7, h = e & 127;
            *(float4*)&Ks[r * QSTR + h] = *(const float4*)&Kg[(size_t)r * H_ + h];
            *(float4*)&Vs[r * QSTR + h] = *(const float4*)&Vg[(size_t)r * H_ + h];
        }
        __syncthreads();

        // S = Q K^T  (4x4 per thread, strided ownership)
        float s[4][4];
#pragma unroll
        for (int i = 0; i < 4; i++)
#pragma unroll
            for (int jj = 0; jj < 4; jj++) s[i][jj] = 0.f;

#pragma unroll 4
        for (int h4 = 0; h4 < 32; h4++) {
            float4 q[4], k[4];
#pragma unroll
            for (int i = 0; i < 4; i++)
                q[i] = *(const float4*)&Qs[(ty + 16 * i) * QSTR + h4 * 4];
#pragma unroll
            for (int jj = 0; jj < 4; jj++)
                k[jj] = *(const float4*)&Ks[(tx + 16 * jj) * QSTR + h4 * 4];
#pragma unroll
            for (int i = 0; i < 4; i++)
#pragma unroll
                for (int jj = 0; jj < 4; jj++) {
                    s[i][jj] = fmaf(q[i].x, k[jj].x, s[i][jj]);
                    s[i][jj] = fmaf(q[i].y, k[jj].y, s[i][jj]);
                    s[i][jj] = fmaf(q[i].z, k[jj].z, s[i][jj]);
                    s[i][jj] = fmaf(q[i].w, k[jj].w, s[i][jj]);
                }
        }

        // Causal mask (only the diagonal tile can have masked entries)
        if (j == qt) {
#pragma unroll
            for (int i = 0; i < 4; i++)
#pragma unroll
                for (int jj = 0; jj < 4; jj++)
                    if (tx + 16 * jj > ty + 16 * i) s[i][jj] = -1e30f;
        }

        // Online softmax update per owned row
#pragma unroll
        for (int i = 0; i < 4; i++) {
            float mx = fmaxf(fmaxf(s[i][0], s[i][1]), fmaxf(s[i][2], s[i][3]));
#pragma unroll
            for (int off = 8; off; off >>= 1)
                mx = fmaxf(mx, __shfl_xor_sync(0xffffffffu, mx, off));
            float mn = fmaxf(m[i], mx);
            float corr = __expf(m[i] - mn);
            float rs = 0.f;
#pragma unroll
            for (int jj = 0; jj < 4; jj++) {
                s[i][jj] = __expf(s[i][jj] - mn);
                rs += s[i][jj];
            }
#pragma unroll
            for (int off = 8; off; off >>= 1)
                rs += __shfl_xor_sync(0xffffffffu, rs, off);
            l[i] = l[i] * corr + rs;
            m[i] = mn;
#pragma unroll
            for (int c = 0; c < 8; c++) o[i][c] *= corr;
#pragma unroll
            for (int jj = 0; jj < 4; jj++)
                Ps[(ty + 16 * i) * PSTR + tx + 16 * jj] = s[i][jj];
        }
        __syncthreads();

        // O += P V
#pragma unroll 4
        for (int jj = 0; jj < BN; jj++) {
            float4 v0 = *(const float4*)&Vs[jj * QSTR + tx * 8];
            float4 v1 = *(const float4*)&Vs[jj * QSTR + tx * 8 + 4];
#pragma unroll
            for (int i = 0; i < 4; i++) {
                float p = Ps[(ty + 16 * i) * PSTR + jj];
                o[i][0] = fmaf(p, v0.x, o[i][0]);
                o[i][1] = fmaf(p, v0.y, o[i][1]);
                o[i][2] = fmaf(p, v0.z, o[i][2]);
                o[i][3] = fmaf(p, v0.w, o[i][3]);
                o[i][4] = fmaf(p, v1.x, o[i][4]);
                o[i][5] = fmaf(p, v1.y, o[i][5]);
                o[i][6] = fmaf(p, v1.z, o[i][6]);
                o[i][7] = fmaf(p, v1.w, o[i][7]);
            }
        }
    }

    // Epilogue: normalize and write
#pragma unroll
    for (int i = 0; i < 4; i++) {
        float inv = 1.f / l[i];
        size_t base = ((size_t)b * T_ + (size_t)qt * BM + ty + 16 * i) * H_ + tx * 8;
        float4 o0 = make_float4(o[i][0] * inv, o[i][1] * inv, o[i][2] * inv, o[i][3] * inv);
        float4 o1 = make_float4(o[i][4] * inv, o[i][5] * inv, o[i][6] * inv, o[i][7] * inv);
        *(float4*)&out[base] = o0;
        *(float4*)&out[base + 4] = o1;
    }
}

extern "C" void kernel_launch(void* const* d_in, const int* in_sizes, int n_in,
                              void* d_out, int out_size) {
    const float* x  = (const float*)d_in[0];
    const float* Wq = (const float*)d_in[1];
    const float* Wk = (const float*)d_in[2];
    const float* Wv = (const float*)d_in[3];
    float* out = (float*)d_out;

    qkv_kernel<<<dim3(256, 3), 256>>>(x, Wq, Wk, Wv);

    const size_t smem = ATTN_SMEM_FLOATS * sizeof(float);  // 118784 B
    cudaFuncSetAttribute(attn_kernel,
                         cudaFuncAttributeMaxDynamicSharedMemorySize, (int)smem);
    attn_kernel<<<dim3(T_ / BM, B_), 256, smem>>>(out);
}

// round 2
// speedup vs baseline: 2.8462x; 2.8462x over previous
#include <cuda_runtime.h>
#include <cstdint>

#define B_ 8
#define T_ 4096
#define C_ 1024
#define H_ 128

// Scratch for Q,K,V projections (tf32-rounded fp32): 48 MB static
__device__ float g_Q[(size_t)B_ * T_ * H_];
__device__ float g_K[(size_t)B_ * T_ * H_];
__device__ float g_V[(size_t)B_ * T_ * H_];

__device__ __forceinline__ float to_tf32(float x) {
    float r;
    asm("cvt.rna.tf32.f32 %0, %1;" : "=f"(r) : "f"(x));
    return r;
}

// D += A(16x8) * B(8x8), tf32 inputs (bits in .f32 regs), fp32 accumulate
__device__ __forceinline__ void mma_tf32(float d[4],
                                         uint32_t a0, uint32_t a1, uint32_t a2, uint32_t a3,
                                         uint32_t b0, uint32_t b1) {
    asm volatile(
        "mma.sync.aligned.m16n8k8.row.col.f32.tf32.tf32.f32 "
        "{%0,%1,%2,%3}, {%4,%5,%6,%7}, {%8,%9}, {%0,%1,%2,%3};\n"
        : "+f"(d[0]), "+f"(d[1]), "+f"(d[2]), "+f"(d[3])
        : "r"(a0), "r"(a1), "r"(a2), "r"(a3), "r"(b0), "r"(b1));
}

// ---------------------------------------------------------------------------
// QKV projection on tensor cores. Y[row,h] = sum_c x[row,c]*W[h,c]
// M=32768, N=128, K=1024. BM=128, BN=128, BK=32. 256 threads = 8 warps.
// grid = (256, 3). Output rounded to tf32 so attn mma truncation is exact.
// ---------------------------------------------------------------------------
#define XS_STR 36   // 36 % 32 == 4 -> conflict-free fragment reads

__global__ __launch_bounds__(256) void qkv_tc_kernel(
    const float* __restrict__ x,
    const float* __restrict__ Wq,
    const float* __restrict__ Wk,
    const float* __restrict__ Wv) {
    __shared__ float Xs[128 * XS_STR];
    __shared__ float Ws[128 * XS_STR];

    const float* W = (blockIdx.y == 0) ? Wq : (blockIdx.y == 1) ? Wk : Wv;
    float* Y       = (blockIdx.y == 0) ? g_Q : (blockIdx.y == 1) ? g_K : g_V;

    const int tid  = threadIdx.x;
    const int lane = tid & 31;
    const int wid  = tid >> 5;
    const int g    = lane >> 2;   // group id (row within frag)
    const int t    = lane & 3;    // thread-in-group (col within frag)
    const int row0 = blockIdx.x * 128;
    const int m0   = wid * 16;

    float acc[16][4];
#pragma unroll
    for (int nf = 0; nf < 16; nf++)
#pragma unroll
        for (int e = 0; e < 4; e++) acc[nf][e] = 0.f;

    for (int k0 = 0; k0 < C_; k0 += 32) {
#pragma unroll
        for (int p = 0; p < 4; p++) {
            int id = tid + p * 256;          // 0..1023 float4s of a 128x32 tile
            int r  = id >> 3;
            int c4 = (id & 7) * 4;
            float4 vx = *(const float4*)&x[(size_t)(row0 + r) * C_ + k0 + c4];
            Xs[r * XS_STR + c4 + 0] = to_tf32(vx.x);
            Xs[r * XS_STR + c4 + 1] = to_tf32(vx.y);
            Xs[r * XS_STR + c4 + 2] = to_tf32(vx.z);
            Xs[r * XS_STR + c4 + 3] = to_tf32(vx.w);
            float4 vw = *(const float4*)&W[(size_t)r * C_ + k0 + c4];
            Ws[r * XS_STR + c4 + 0] = to_tf32(vw.x);
            Ws[r * XS_STR + c4 + 1] = to_tf32(vw.y);
            Ws[r * XS_STR + c4 + 2] = to_tf32(vw.z);
            Ws[r * XS_STR + c4 + 3] = to_tf32(vw.w);
        }
        __syncthreads();
#pragma unroll
        for (int kc = 0; kc < 4; kc++) {
            uint32_t a0 = __float_as_uint(Xs[(m0 + g)     * XS_STR + kc * 8 + t]);
            uint32_t a1 = __float_as_uint(Xs[(m0 + g + 8) * XS_STR + kc * 8 + t]);
            uint32_t a2 = __float_as_uint(Xs[(m0 + g)     * XS_STR + kc * 8 + t + 4]);
            uint32_t a3 = __float_as_uint(Xs[(m0 + g + 8) * XS_STR + kc * 8 + t + 4]);
#pragma unroll
            for (int nf = 0; nf < 16; nf++) {
                uint32_t b0 = __float_as_uint(Ws[(nf * 8 + g) * XS_STR + kc * 8 + t]);
                uint32_t b1 = __float_as_uint(Ws[(nf * 8 + g) * XS_STR + kc * 8 + t + 4]);
                mma_tf32(acc[nf], a0, a1, a2, a3, b0, b1);
            }
        }
        __syncthreads();
    }

#pragma unroll
    for (int nf = 0; nf < 16; nf++) {
        int col = nf * 8 + 2 * t;
        size_t r0 = (size_t)(row0 + m0 + g) * H_ + col;
        size_t r1 = (size_t)(row0 + m0 + g + 8) * H_ + col;
        float2 o0 = make_float2(to_tf32(acc[nf][0]), to_tf32(acc[nf][1]));
        float2 o1 = make_float2(to_tf32(acc[nf][2]), to_tf32(acc[nf][3]));
        *(float2*)&Y[r0] = o0;
        *(float2*)&Y[r1] = o1;
    }
}

// ---------------------------------------------------------------------------
// Flash attention (causal) on tensor cores. BM=BN=64, HD=128.
// 128 threads = 4 warps; warp w owns q-rows [w*16, w*16+16).
// S and O live in m16n8k8 C-fragments. P re-shaped via smem.
// ---------------------------------------------------------------------------
#define QSTR 132   // 132 % 32 == 4
#define VSTR 136   // 136 % 32 == 8
#define PSTR 68    //  68 % 32 == 4
#define ATTN_SMEM_BYTES ((64 * QSTR + 64 * QSTR + 64 * VSTR + 64 * PSTR) * 4)

__global__ __launch_bounds__(128) void attn_tc_kernel(float* __restrict__ out) {
    extern __shared__ float sm[];
    float* Qs = sm;                      // [64][132]
    float* Ks = Qs + 64 * QSTR;          // [64][132]
    float* Vs = Ks + 64 * QSTR;          // [64][136]
    float* Ps = Vs + 64 * VSTR;          // [64][68]

    const int b   = blockIdx.y;
    const int qt  = (int)gridDim.x - 1 - (int)blockIdx.x;  // big tiles first
    const int tid = threadIdx.x;
    const int lane = tid & 31;
    const int wid  = tid >> 5;
    const int g    = lane >> 2;
    const int t    = lane & 3;
    const int m0   = wid * 16;
    const float scale = 0.08838834764831843f;  // 1/sqrt(128)

    // Load Q tile (already tf32-rounded)
    const float* Qg = g_Q + ((size_t)b * T_ + (size_t)qt * 64) * H_;
#pragma unroll
    for (int p = 0; p < 16; p++) {
        int id = tid + p * 128;
        int r = id >> 5, h = (id & 31) * 4;
        *(float4*)&Qs[r * QSTR + h] = *(const float4*)&Qg[(size_t)r * H_ + h];
    }

    float of[16][4];
#pragma unroll
    for (int nf = 0; nf < 16; nf++)
#pragma unroll
        for (int e = 0; e < 4; e++) of[nf][e] = 0.f;
    float mrow[2] = {-1e30f, -1e30f};
    float lrow[2] = {0.f, 0.f};

    for (int j = 0; j <= qt; j++) {
        __syncthreads();  // previous iteration done reading Ks/Vs
        const float* Kg = g_K + ((size_t)b * T_ + (size_t)j * 64) * H_;
        const float* Vg = g_V + ((size_t)b * T_ + (size_t)j * 64) * H_;
#pragma unroll
        for (int p = 0; p < 16; p++) {
            int id = tid + p * 128;
            int r = id >> 5, h = (id & 31) * 4;
            *(float4*)&Ks[r * QSTR + h] = *(const float4*)&Kg[(size_t)r * H_ + h];
            *(float4*)&Vs[r * VSTR + h] = *(const float4*)&Vg[(size_t)r * H_ + h];
        }
        __syncthreads();

        // ---- S = Q K^T : warp tile 16x64, 8 n-frags, 16 k-chunks
        float s[8][4];
#pragma unroll
        for (int nf = 0; nf < 8; nf++)
#pragma unroll
            for (int e = 0; e < 4; e++) s[nf][e] = 0.f;

#pragma unroll
        for (int kc = 0; kc < 16; kc++) {
            uint32_t a0 = __float_as_uint(Qs[(m0 + g)     * QSTR + kc * 8 + t]);
            uint32_t a1 = __float_as_uint(Qs[(m0 + g + 8) * QSTR + kc * 8 + t]);
            uint32_t a2 = __float_as_uint(Qs[(m0 + g)     * QSTR + kc * 8 + t + 4]);
            uint32_t a3 = __float_as_uint(Qs[(m0 + g + 8) * QSTR + kc * 8 + t + 4]);
#pragma unroll
            for (int nf = 0; nf < 8; nf++) {
                uint32_t b0 = __float_as_uint(Ks[(nf * 8 + g) * QSTR + kc * 8 + t]);
                uint32_t b1 = __float_as_uint(Ks[(nf * 8 + g) * QSTR + kc * 8 + t + 4]);
                mma_tf32(s[nf], a0, a1, a2, a3, b0, b1);
            }
        }

        // ---- scale + causal mask (diagonal tile only)
#pragma unroll
        for (int nf = 0; nf < 8; nf++)
#pragma unroll
            for (int e = 0; e < 4; e++) s[nf][e] *= scale;
        if (j == qt) {
#pragma unroll
            for (int nf = 0; nf < 8; nf++) {
                int c0 = nf * 8 + 2 * t, c1 = c0 + 1;
                int r0 = m0 + g, r1 = r0 + 8;
                if (c0 > r0) s[nf][0] = -1e30f;
                if (c1 > r0) s[nf][1] = -1e30f;
                if (c0 > r1) s[nf][2] = -1e30f;
                if (c1 > r1) s[nf][3] = -1e30f;
            }
        }

        // ---- online softmax (rows g and g+8 of warp tile)
        float mx0 = -1e30f, mx1 = -1e30f;
#pragma unroll
        for (int nf = 0; nf < 8; nf++) {
            mx0 = fmaxf(mx0, fmaxf(s[nf][0], s[nf][1]));
            mx1 = fmaxf(mx1, fmaxf(s[nf][2], s[nf][3]));
        }
        mx0 = fmaxf(mx0, __shfl_xor_sync(0xffffffffu, mx0, 1));
        mx0 = fmaxf(mx0, __shfl_xor_sync(0xffffffffu, mx0, 2));
        mx1 = fmaxf(mx1, __shfl_xor_sync(0xffffffffu, mx1, 1));
        mx1 = fmaxf(mx1, __shfl_xor_sync(0xffffffffu, mx1, 2));
        float mn0 = fmaxf(mrow[0], mx0), mn1 = fmaxf(mrow[1], mx1);
        float corr0 = __expf(mrow[0] - mn0), corr1 = __expf(mrow[1] - mn1);

        float rs0 = 0.f, rs1 = 0.f;
#pragma unroll
        for (int nf = 0; nf < 8; nf++) {
            s[nf][0] = __expf(s[nf][0] - mn0);
            s[nf][1] = __expf(s[nf][1] - mn0);
            s[nf][2] = __expf(s[nf][2] - mn1);
            s[nf][3] = __expf(s[nf][3] - mn1);
            rs0 += s[nf][0] + s[nf][1];
            rs1 += s[nf][2] + s[nf][3];
        }
        rs0 += __shfl_xor_sync(0xffffffffu, rs0, 1);
        rs0 += __shfl_xor_sync(0xffffffffu, rs0, 2);
        rs1 += __shfl_xor_sync(0xffffffffu, rs1, 1);
        rs1 += __shfl_xor_sync(0xffffffffu, rs1, 2);
        lrow[0] = lrow[0] * corr0 + rs0;
        lrow[1] = lrow[1] * corr1 + rs1;
        mrow[0] = mn0; mrow[1] = mn1;

        // rescale O, stash P (tf32) into smem for fragment reshape
#pragma unroll
        for (int nf = 0; nf < 16; nf++) {
            of[nf][0] *= corr0; of[nf][1] *= corr0;
            of[nf][2] *= corr1; of[nf][3] *= corr1;
        }
#pragma unroll
        for (int nf = 0; nf < 8; nf++) {
            int c = nf * 8 + 2 * t;
            Ps[(m0 + g)     * PSTR + c]     = to_tf32(s[nf][0]);
            Ps[(m0 + g)     * PSTR + c + 1] = to_tf32(s[nf][1]);
            Ps[(m0 + g + 8) * PSTR + c]     = to_tf32(s[nf][2]);
            Ps[(m0 + g + 8) * PSTR + c + 1] = to_tf32(s[nf][3]);
        }
        __syncwarp();

        // ---- O += P V : k-dim = 64 kv positions, 8 k-chunks, 16 n-frags
#pragma unroll
        for (int kc = 0; kc < 8; kc++) {
            uint32_t a0 = __float_as_uint(Ps[(m0 + g)     * PSTR + kc * 8 + t]);
            uint32_t a1 = __float_as_uint(Ps[(m0 + g + 8) * PSTR + kc * 8 + t]);
            uint32_t a2 = __float_as_uint(Ps[(m0 + g)     * PSTR + kc * 8 + t + 4]);
            uint32_t a3 = __float_as_uint(Ps[(m0 + g + 8) * PSTR + kc * 8 + t + 4]);
#pragma unroll
            for (int nf = 0; nf < 16; nf++) {
                uint32_t b0 = __float_as_uint(Vs[(kc * 8 + t)     * VSTR + nf * 8 + g]);
                uint32_t b1 = __float_as_uint(Vs[(kc * 8 + t + 4) * VSTR + nf * 8 + g]);
                mma_tf32(of[nf], a0, a1, a2, a3, b0, b1);
            }
        }
    }

    // ---- epilogue
    float inv0 = 1.f / lrow[0], inv1 = 1.f / lrow[1];
    size_t orow0 = (size_t)b * T_ + (size_t)qt * 64 + m0 + g;
#pragma unroll
    for (int nf = 0; nf < 16; nf++) {
        int col = nf * 8 + 2 * t;
        float2 o0 = make_float2(of[nf][0] * inv0, of[nf][1] * inv0);
        float2 o1 = make_float2(of[nf][2] * inv1, of[nf][3] * inv1);
        *(float2*)&out[orow0 * H_ + col] = o0;
        *(float2*)&out[(orow0 + 8) * H_ + col] = o1;
    }
}

extern "C" void kernel_launch(void* const* d_in, const int* in_sizes, int n_in,
                              void* d_out, int out_size) {
    const float* x  = (const float*)d_in[0];
    const float* Wq = (const float*)d_in[1];
    const float* Wk = (const float*)d_in[2];
    const float* Wv = (const float*)d_in[3];
    float* out = (float*)d_out;

    qkv_tc_kernel<<<dim3(256, 3), 256>>>(x, Wq, Wk, Wv);

    cudaFuncSetAttribute(attn_tc_kernel,
                         cudaFuncAttributeMaxDynamicSharedMemorySize,
                         ATTN_SMEM_BYTES);
    attn_tc_kernel<<<dim3(T_ / 64, B_), 128, ATTN_SMEM_BYTES>>>(out);
}

// round 3
// speedup vs baseline: 3.3144x; 1.1645x over previous
#include <cuda_runtime.h>
#include <cstdint>

#define B_ 8
#define T_ 4096
#define C_ 1024
#define H_ 128

// Scratch for Q,K,V projections (tf32-rounded fp32): 48 MB static
__device__ float g_Q[(size_t)B_ * T_ * H_];
__device__ float g_K[(size_t)B_ * T_ * H_];
__device__ float g_V[(size_t)B_ * T_ * H_];

__device__ __forceinline__ float to_tf32(float x) {
    float r;
    asm("cvt.rna.tf32.f32 %0, %1;" : "=f"(r) : "f"(x));
    return r;
}

__device__ __forceinline__ float fast_exp2(float x) {
    float r;
    asm("ex2.approx.ftz.f32 %0, %1;" : "=f"(r) : "f"(x));
    return r;
}

// D += A(16x8) * B(8x8), tf32 inputs, fp32 accumulate
__device__ __forceinline__ void mma_tf32(float d[4],
                                         uint32_t a0, uint32_t a1, uint32_t a2, uint32_t a3,
                                         uint32_t b0, uint32_t b1) {
    asm volatile(
        "mma.sync.aligned.m16n8k8.row.col.f32.tf32.tf32.f32 "
        "{%0,%1,%2,%3}, {%4,%5,%6,%7}, {%8,%9}, {%0,%1,%2,%3};\n"
        : "+f"(d[0]), "+f"(d[1]), "+f"(d[2]), "+f"(d[3])
        : "r"(a0), "r"(a1), "r"(a2), "r"(a3), "r"(b0), "r"(b1));
}

#define CPA16(dst, src) \
    asm volatile("cp.async.cg.shared.global [%0], [%1], 16;" :: "r"(dst), "l"(src))
#define CP_COMMIT() asm volatile("cp.async.commit_group;")
#define CP_WAIT0()  asm volatile("cp.async.wait_group 0;")
#define CP_WAIT1()  asm volatile("cp.async.wait_group 1;")

// ---------------------------------------------------------------------------
// QKV projection. M=32768, N=128, K=1024. BM=128,BN=128,BK=32. 8 warps.
// Register-prefetch pipeline over the K dim. grid=(256,3).
// ---------------------------------------------------------------------------
#define XS_STR 36

__global__ __launch_bounds__(256) void qkv_tc_kernel(
    const float* __restrict__ x,
    const float* __restrict__ Wq,
    const float* __restrict__ Wk,
    const float* __restrict__ Wv) {
    __shared__ float Xs[128 * XS_STR];
    __shared__ float Ws[128 * XS_STR];

    const float* W = (blockIdx.y == 0) ? Wq : (blockIdx.y == 1) ? Wk : Wv;
    float* Y       = (blockIdx.y == 0) ? g_Q : (blockIdx.y == 1) ? g_K : g_V;

    const int tid  = threadIdx.x;
    const int lane = tid & 31;
    const int wid  = tid >> 5;
    const int g    = lane >> 2;
    const int t    = lane & 3;
    const int row0 = blockIdx.x * 128;
    const int m0   = wid * 16;

    float acc[16][4];
#pragma unroll
    for (int nf = 0; nf < 16; nf++)
#pragma unroll
        for (int e = 0; e < 4; e++) acc[nf][e] = 0.f;

    // prefetch first tile into registers
    float4 vx[4], vw[4];
#pragma unroll
    for (int p = 0; p < 4; p++) {
        int id = tid + p * 256;
        int r = id >> 3, c4 = (id & 7) * 4;
        vx[p] = *(const float4*)&x[(size_t)(row0 + r) * C_ + c4];
        vw[p] = *(const float4*)&W[(size_t)r * C_ + c4];
    }

    for (int k0 = 0; k0 < C_; k0 += 32) {
#pragma unroll
        for (int p = 0; p < 4; p++) {
            int id = tid + p * 256;
            int r = id >> 3, c4 = (id & 7) * 4;
            Xs[r * XS_STR + c4 + 0] = to_tf32(vx[p].x);
            Xs[r * XS_STR + c4 + 1] = to_tf32(vx[p].y);
            Xs[r * XS_STR + c4 + 2] = to_tf32(vx[p].z);
            Xs[r * XS_STR + c4 + 3] = to_tf32(vx[p].w);
            Ws[r * XS_STR + c4 + 0] = to_tf32(vw[p].x);
            Ws[r * XS_STR + c4 + 1] = to_tf32(vw[p].y);
            Ws[r * XS_STR + c4 + 2] = to_tf32(vw[p].z);
            Ws[r * XS_STR + c4 + 3] = to_tf32(vw[p].w);
        }
        __syncthreads();

        if (k0 + 32 < C_) {
#pragma unroll
            for (int p = 0; p < 4; p++) {
                int id = tid + p * 256;
                int r = id >> 3, c4 = (id & 7) * 4;
                vx[p] = *(const float4*)&x[(size_t)(row0 + r) * C_ + k0 + 32 + c4];
                vw[p] = *(const float4*)&W[(size_t)r * C_ + k0 + 32 + c4];
            }
        }

#pragma unroll
        for (int kc = 0; kc < 4; kc++) {
            uint32_t a0 = __float_as_uint(Xs[(m0 + g)     * XS_STR + kc * 8 + t]);
            uint32_t a1 = __float_as_uint(Xs[(m0 + g + 8) * XS_STR + kc * 8 + t]);
            uint32_t a2 = __float_as_uint(Xs[(m0 + g)     * XS_STR + kc * 8 + t + 4]);
            uint32_t a3 = __float_as_uint(Xs[(m0 + g + 8) * XS_STR + kc * 8 + t + 4]);
#pragma unroll
            for (int nf = 0; nf < 16; nf++) {
                uint32_t b0 = __float_as_uint(Ws[(nf * 8 + g) * XS_STR + kc * 8 + t]);
                uint32_t b1 = __float_as_uint(Ws[(nf * 8 + g) * XS_STR + kc * 8 + t + 4]);
                mma_tf32(acc[nf], a0, a1, a2, a3, b0, b1);
            }
        }
        __syncthreads();
    }

#pragma unroll
    for (int nf = 0; nf < 16; nf++) {
        int col = nf * 8 + 2 * t;
        size_t r0 = (size_t)(row0 + m0 + g) * H_ + col;
        size_t r1 = (size_t)(row0 + m0 + g + 8) * H_ + col;
        *(float2*)&Y[r0] = make_float2(to_tf32(acc[nf][0]), to_tf32(acc[nf][1]));
        *(float2*)&Y[r1] = make_float2(to_tf32(acc[nf][2]), to_tf32(acc[nf][3]));
    }
}

// ---------------------------------------------------------------------------
// Flash attention (causal). BM=128, BN=64, HD=128. 256 threads = 8 warps,
// warp w owns q-rows [w*16, w*16+16). Double-buffered cp.async K/V.
// P reshaped C-frag -> A-frag with shuffles (no smem P).
// ---------------------------------------------------------------------------
#define QSTR 132   // % 32 == 4
#define VSTR 136   // % 32 == 8
#define ATTN_SMEM_BYTES ((128 * QSTR + 2 * 64 * QSTR + 2 * 64 * VSTR) * 4)  // 200 KB

__global__ __launch_bounds__(256) void attn_tc_kernel(float* __restrict__ out) {
    extern __shared__ float sm[];
    float* Qs  = sm;                     // [128][132]
    float* Ks0 = Qs + 128 * QSTR;        // [64][132] x2
    float* Ks1 = Ks0 + 64 * QSTR;
    float* Vs0 = Ks1 + 64 * QSTR;        // [64][136] x2
    float* Vs1 = Vs0 + 64 * VSTR;

    const int b   = blockIdx.y;
    const int qt  = (int)gridDim.x - 1 - (int)blockIdx.x;  // big tiles first
    const int tid = threadIdx.x;
    const int lane = tid & 31;
    const int wid  = tid >> 5;
    const int g    = lane >> 2;
    const int t    = lane & 3;
    const int m0   = wid * 16;
    // scale * log2(e): softmax in exp2 domain
    const float scale2 = 0.08838834764831843f * 1.4426950408889634f;

    const float* Kg = g_K + (size_t)b * T_ * H_;
    const float* Vg = g_V + (size_t)b * T_ * H_;
    const uint32_t ks0u = (uint32_t)__cvta_generic_to_shared(Ks0);
    const uint32_t ks1u = (uint32_t)__cvta_generic_to_shared(Ks1);
    const uint32_t vs0u = (uint32_t)__cvta_generic_to_shared(Vs0);
    const uint32_t vs1u = (uint32_t)__cvta_generic_to_shared(Vs1);

    const int nj = 2 * qt + 2;

    // issue async K/V tile j into buffer sel
    auto issue_kv = [&](int j, int sel) {
        uint32_t ku = sel ? ks1u : ks0u;
        uint32_t vu = sel ? vs1u : vs0u;
        const float* kp = Kg + (size_t)j * 64 * H_;
        const float* vp = Vg + (size_t)j * 64 * H_;
#pragma unroll
        for (int p = 0; p < 8; p++) {
            int id = tid + p * 256;
            int r = id >> 5, h = (id & 31) * 4;
            CPA16(ku + (uint32_t)(r * QSTR + h) * 4, kp + (size_t)r * H_ + h);
            CPA16(vu + (uint32_t)(r * VSTR + h) * 4, vp + (size_t)r * H_ + h);
        }
        CP_COMMIT();
    };

    issue_kv(0, 0);

    // load Q tile (sync; overlaps with the async KV prefetch)
    const float* Qg = g_Q + ((size_t)b * T_ + (size_t)qt * 128) * H_;
#pragma unroll
    for (int p = 0; p < 16; p++) {
        int id = tid + p * 256;
        int r = id >> 5, h = (id & 31) * 4;
        *(float4*)&Qs[r * QSTR + h] = *(const float4*)&Qg[(size_t)r * H_ + h];
    }

    float of[16][4];
#pragma unroll
    for (int nf = 0; nf < 16; nf++)
#pragma unroll
        for (int e = 0; e < 4; e++) of[nf][e] = 0.f;
    float mrow[2] = {-1e30f, -1e30f};
    float lrow[2] = {0.f, 0.f};

    const int lo  = g * 4 + (t >> 1);   // shfl source lane for P reshape
    const int par = t & 1;

    for (int j = 0; j < nj; j++) {
        const float* Ksc = (j & 1) ? Ks1 : Ks0;
        const float* Vsc = (j & 1) ? Vs1 : Vs0;
        if (j + 1 < nj) {
            issue_kv(j + 1, (j + 1) & 1);
            CP_WAIT1();
        } else {
            CP_WAIT0();
        }
        __syncthreads();   // buffer j ready for all warps

        // ---- S = Q K^T : 16x64 per warp
        float s[8][4];
#pragma unroll
        for (int nf = 0; nf < 8; nf++)
#pragma unroll
            for (int e = 0; e < 4; e++) s[nf][e] = 0.f;

#pragma unroll
        for (int kc = 0; kc < 16; kc++) {
            uint32_t a0 = __float_as_uint(Qs[(m0 + g)     * QSTR + kc * 8 + t]);
            uint32_t a1 = __float_as_uint(Qs[(m0 + g + 8) * QSTR + kc * 8 + t]);
            uint32_t a2 = __float_as_uint(Qs[(m0 + g)     * QSTR + kc * 8 + t + 4]);
            uint32_t a3 = __float_as_uint(Qs[(m0 + g + 8) * QSTR + kc * 8 + t + 4]);
#pragma unroll
            for (int nf = 0; nf < 8; nf++) {
                uint32_t b0 = __float_as_uint(Ksc[(nf * 8 + g) * QSTR + kc * 8 + t]);
                uint32_t b1 = __float_as_uint(Ksc[(nf * 8 + g) * QSTR + kc * 8 + t + 4]);
                mma_tf32(s[nf], a0, a1, a2, a3, b0, b1);
            }
        }

        // ---- to exp2 domain + causal mask (only near-diagonal tiles)
#pragma unroll
        for (int nf = 0; nf < 8; nf++)
#pragma unroll
            for (int e = 0; e < 4; e++) s[nf][e] *= scale2;

        const int jb = j * 64;
        if (jb + 63 > qt * 128 + m0) {
            const int qr0 = qt * 128 + m0 + g;
            const int qr1 = qr0 + 8;
#pragma unroll
            for (int nf = 0; nf < 8; nf++) {
                int c0 = jb + nf * 8 + 2 * t, c1 = c0 + 1;
                if (c0 > qr0) s[nf][0] = -1e30f;
                if (c1 > qr0) s[nf][1] = -1e30f;
                if (c0 > qr1) s[nf][2] = -1e30f;
                if (c1 > qr1) s[nf][3] = -1e30f;
            }
        }

        // ---- online softmax (exp2 domain)
        float mx0 = -1e30f, mx1 = -1e30f;
#pragma unroll
        for (int nf = 0; nf < 8; nf++) {
            mx0 = fmaxf(mx0, fmaxf(s[nf][0], s[nf][1]));
            mx1 = fmaxf(mx1, fmaxf(s[nf][2], s[nf][3]));
        }
        mx0 = fmaxf(mx0, __shfl_xor_sync(0xffffffffu, mx0, 1));
        mx0 = fmaxf(mx0, __shfl_xor_sync(0xffffffffu, mx0, 2));
        mx1 = fmaxf(mx1, __shfl_xor_sync(0xffffffffu, mx1, 1));
        mx1 = fmaxf(mx1, __shfl_xor_sync(0xffffffffu, mx1, 2));
        float mn0 = fmaxf(mrow[0], mx0), mn1 = fmaxf(mrow[1], mx1);
        float corr0 = fast_exp2(mrow[0] - mn0), corr1 = fast_exp2(mrow[1] - mn1);

        float rs0 = 0.f, rs1 = 0.f;
#pragma unroll
        for (int nf = 0; nf < 8; nf++) {
            s[nf][0] = fast_exp2(s[nf][0] - mn0);
            s[nf][1] = fast_exp2(s[nf][1] - mn0);
            s[nf][2] = fast_exp2(s[nf][2] - mn1);
            s[nf][3] = fast_exp2(s[nf][3] - mn1);
            rs0 += s[nf][0] + s[nf][1];
            rs1 += s[nf][2] + s[nf][3];
        }
        rs0 += __shfl_xor_sync(0xffffffffu, rs0, 1);
        rs0 += __shfl_xor_sync(0xffffffffu, rs0, 2);
        rs1 += __shfl_xor_sync(0xffffffffu, rs1, 1);
        rs1 += __shfl_xor_sync(0xffffffffu, rs1, 2);
        lrow[0] = lrow[0] * corr0 + rs0;
        lrow[1] = lrow[1] * corr1 + rs1;
        mrow[0] = mn0; mrow[1] = mn1;

#pragma unroll
        for (int nf = 0; nf < 16; nf++) {
            of[nf][0] *= corr0; of[nf][1] *= corr0;
            of[nf][2] *= corr1; of[nf][3] *= corr1;
        }

        // P to tf32 bits for the mma
#pragma unroll
        for (int nf = 0; nf < 8; nf++)
#pragma unroll
            for (int e = 0; e < 4; e++) s[nf][e] = to_tf32(s[nf][e]);

        // ---- O += P V, P reshaped C-frag -> A-frag via shuffles
#pragma unroll
        for (int kc = 0; kc < 8; kc++) {
            float x0 = __shfl_sync(0xffffffffu, s[kc][0], lo);
            float x1 = __shfl_sync(0xffffffffu, s[kc][1], lo);
            float x2 = __shfl_sync(0xffffffffu, s[kc][2], lo);
            float x3 = __shfl_sync(0xffffffffu, s[kc][3], lo);
            float y0 = __shfl_sync(0xffffffffu, s[kc][0], lo + 2);
            float y1 = __shfl_sync(0xffffffffu, s[kc][1], lo + 2);
            float y2 = __shfl_sync(0xffffffffu, s[kc][2], lo + 2);
            float y3 = __shfl_sync(0xffffffffu, s[kc][3], lo + 2);
            uint32_t a0 = __float_as_uint(par ? x1 : x0);
            uint32_t a1 = __float_as_uint(par ? x3 : x2);
            uint32_t a2 = __float_as_uint(par ? y1 : y0);
            uint32_t a3 = __float_as_uint(par ? y3 : y2);
#pragma unroll
            for (int nf = 0; nf < 16; nf++) {
                uint32_t b0 = __float_as_uint(Vsc[(kc * 8 + t)     * VSTR + nf * 8 + g]);
                uint32_t b1 = __float_as_uint(Vsc[(kc * 8 + t + 4) * VSTR + nf * 8 + g]);
                mma_tf32(of[nf], a0, a1, a2, a3, b0, b1);
            }
        }
        __syncthreads();   // all warps done with buffer j before it's refilled
    }

    // ---- epilogue
    float inv0 = 1.f / lrow[0], inv1 = 1.f / lrow[1];
    size_t orow0 = (size_t)b * T_ + (size_t)qt * 128 + m0 + g;
#pragma unroll
    for (int nf = 0; nf < 16; nf++) {
        int col = nf * 8 + 2 * t;
        *(float2*)&out[orow0 * H_ + col] =
            make_float2(of[nf][0] * inv0, of[nf][1] * inv0);
        *(float2*)&out[(orow0 + 8) * H_ + col] =
            make_float2(of[nf][2] * inv1, of[nf][3] * inv1);
    }
}

extern "C" void kernel_launch(void* const* d_in, const int* in_sizes, int n_in,
                              void* d_out, int out_size) {
    const float* x  = (const float*)d_in[0];
    const float* Wq = (const float*)d_in[1];
    const float* Wk = (const float*)d_in[2];
    const float* Wv = (const float*)d_in[3];
    float* out = (float*)d_out;

    qkv_tc_kernel<<<dim3(256, 3), 256>>>(x, Wq, Wk, Wv);

    cudaFuncSetAttribute(attn_tc_kernel,
                         cudaFuncAttributeMaxDynamicSharedMemorySize,
                         ATTN_SMEM_BYTES);
    attn_tc_kernel<<<dim3(T_ / 128, B_), 256, ATTN_SMEM_BYTES>>>(out);
}

// round 4
// speedup vs baseline: 6.3552x; 1.9174x over previous
#include <cuda_runtime.h>
#include <cuda_fp16.h>
#include <cstdint>

#define B_ 8
#define T_ 4096
#define C_ 1024
#define H_ 128

// Q,K,V scratch in fp16: 3 * 32768*128*2 = 24 MB
__device__ __half g_Q[(size_t)B_ * T_ * H_];
__device__ __half g_K[(size_t)B_ * T_ * H_];
__device__ __half g_V[(size_t)B_ * T_ * H_];

__device__ __forceinline__ float fast_exp2(float x) {
    float r;
    asm("ex2.approx.ftz.f32 %0, %1;" : "=f"(r) : "f"(x));
    return r;
}

// D += A(16x16) * B(16x8), fp16 inputs, fp32 accumulate
__device__ __forceinline__ void mma_f16(float d[4],
                                        uint32_t a0, uint32_t a1, uint32_t a2, uint32_t a3,
                                        uint32_t b0, uint32_t b1) {
    asm volatile(
        "mma.sync.aligned.m16n8k16.row.col.f32.f16.f16.f32 "
        "{%0,%1,%2,%3}, {%4,%5,%6,%7}, {%8,%9}, {%0,%1,%2,%3};\n"
        : "+f"(d[0]), "+f"(d[1]), "+f"(d[2]), "+f"(d[3])
        : "r"(a0), "r"(a1), "r"(a2), "r"(a3), "r"(b0), "r"(b1));
}

__device__ __forceinline__ void ldsm_x4(uint32_t& r0, uint32_t& r1, uint32_t& r2, uint32_t& r3,
                                        uint32_t addr) {
    asm volatile("ldmatrix.sync.aligned.m8n8.x4.shared.b16 {%0,%1,%2,%3}, [%4];"
                 : "=r"(r0), "=r"(r1), "=r"(r2), "=r"(r3) : "r"(addr));
}
__device__ __forceinline__ void ldsm_x4_t(uint32_t& r0, uint32_t& r1, uint32_t& r2, uint32_t& r3,
                                          uint32_t addr) {
    asm volatile("ldmatrix.sync.aligned.m8n8.x4.trans.shared.b16 {%0,%1,%2,%3}, [%4];"
                 : "=r"(r0), "=r"(r1), "=r"(r2), "=r"(r3) : "r"(addr));
}

#define CPA16(dst, src) \
    asm volatile("cp.async.cg.shared.global [%0], [%1], 16;" :: "r"(dst), "l"(src))
#define CP_COMMIT() asm volatile("cp.async.commit_group;")
#define CP_WAIT1()  asm volatile("cp.async.wait_group 1;")
#define CP_WAIT2()  asm volatile("cp.async.wait_group 2;")

__device__ __forceinline__ uint32_t pack_h2(float a, float b) {
    __half2 h = __floats2half2_rn(a, b);
    return *(uint32_t*)&h;
}

// ---------------------------------------------------------------------------
// QKV projection, fp16 tensor cores. M=32768, N=128, K=1024.
// BM=128, BN=128, BK=32. 256 threads = 8 warps. grid=(256,3).
// ---------------------------------------------------------------------------
#define XSTRH 40   // half stride: 32 + 8 pad; 80B rows (odd*16B -> ldmatrix clean)

__global__ __launch_bounds__(256) void qkv_tc_kernel(
    const float* __restrict__ x,
    const float* __restrict__ Wq,
    const float* __restrict__ Wk,
    const float* __restrict__ Wv) {
    __shared__ __half Xs[128 * XSTRH];
    __shared__ __half Ws[128 * XSTRH];

    const float* W = (blockIdx.y == 0) ? Wq : (blockIdx.y == 1) ? Wk : Wv;
    __half* Y      = (blockIdx.y == 0) ? g_Q : (blockIdx.y == 1) ? g_K : g_V;

    const int tid  = threadIdx.x;
    const int lane = tid & 31;
    const int wid  = tid >> 5;
    const int g    = lane >> 2;
    const int t    = lane & 3;
    const int row0 = blockIdx.x * 128;
    const int m0   = wid * 16;

    const uint32_t xs_u = (uint32_t)__cvta_generic_to_shared(Xs);
    const uint32_t ws_u = (uint32_t)__cvta_generic_to_shared(Ws);
    // ldmatrix per-lane address components
    const int lrow = lane & 15;
    const int lcol = (lane >> 4) * 16;   // bytes

    float acc[16][4];
#pragma unroll
    for (int nf = 0; nf < 16; nf++)
#pragma unroll
        for (int e = 0; e < 4; e++) acc[nf][e] = 0.f;

    float4 vx[4], vw[4];
#pragma unroll
    for (int p = 0; p < 4; p++) {
        int id = tid + p * 256;
        int r = id >> 3, c4 = (id & 7) * 4;
        vx[p] = *(const float4*)&x[(size_t)(row0 + r) * C_ + c4];
        vw[p] = *(const float4*)&W[(size_t)r * C_ + c4];
    }

    for (int k0 = 0; k0 < C_; k0 += 32) {
#pragma unroll
        for (int p = 0; p < 4; p++) {
            int id = tid + p * 256;
            int r = id >> 3, c4 = (id & 7) * 4;
            uint32_t h0 = pack_h2(vx[p].x, vx[p].y);
            uint32_t h1 = pack_h2(vx[p].z, vx[p].w);
            *(uint2*)&Xs[r * XSTRH + c4] = make_uint2(h0, h1);
            h0 = pack_h2(vw[p].x, vw[p].y);
            h1 = pack_h2(vw[p].z, vw[p].w);
            *(uint2*)&Ws[r * XSTRH + c4] = make_uint2(h0, h1);
        }
        __syncthreads();

        if (k0 + 32 < C_) {
#pragma unroll
            for (int p = 0; p < 4; p++) {
                int id = tid + p * 256;
                int r = id >> 3, c4 = (id & 7) * 4;
                vx[p] = *(const float4*)&x[(size_t)(row0 + r) * C_ + k0 + 32 + c4];
                vw[p] = *(const float4*)&W[(size_t)r * C_ + k0 + 32 + c4];
            }
        }

#pragma unroll
        for (int kc = 0; kc < 2; kc++) {
            uint32_t a0, a1, a2, a3;
            ldsm_x4(a0, a1, a2, a3,
                    xs_u + (uint32_t)((m0 + lrow) * XSTRH * 2 + kc * 32 + lcol));
#pragma unroll
            for (int r = 0; r < 8; r++) {
                uint32_t b00, b01, b10, b11;
                ldsm_x4(b00, b01, b10, b11,
                        ws_u + (uint32_t)((16 * r + lrow) * XSTRH * 2 + kc * 32 + lcol));
                mma_f16(acc[2 * r], a0, a1, a2, a3, b00, b10);
                mma_f16(acc[2 * r + 1], a0, a1, a2, a3, b01, b11);
            }
        }
        __syncthreads();
    }

#pragma unroll
    for (int nf = 0; nf < 16; nf++) {
        int col = nf * 8 + 2 * t;
        size_t r0 = (size_t)(row0 + m0 + g) * H_ + col;
        size_t r1 = (size_t)(row0 + m0 + g + 8) * H_ + col;
        *(uint32_t*)&Y[r0] = pack_h2(acc[nf][0], acc[nf][1]);
        *(uint32_t*)&Y[r1] = pack_h2(acc[nf][2], acc[nf][3]);
    }
}

// ---------------------------------------------------------------------------
// Flash attention (causal), fp16 mma. BM=64, BN=64, HD=128.
// 128 threads = 4 warps; warp w owns q-rows [w*16, w*16+16).
// K double-buffered, V single-buffered (overlaps S+softmax).
// S C-frags pack directly into PV A-frags (no reshape).
// 3 CTAs/SM.
// ---------------------------------------------------------------------------
#define KSTRH 136                 // 128 + 8 halfs; 272B rows (17*16B)
#define SM_Q  0                   // 64*272 = 17408 B
#define SM_K0 17408
#define SM_K1 (17408 * 2)
#define SM_V  (17408 * 3)
#define ATTN_SMEM_BYTES (17408 * 4)   // 69632 B

__global__ __launch_bounds__(128, 3) void attn_tc_kernel(float* __restrict__ out) {
    extern __shared__ __half smh[];
    const uint32_t sm_u = (uint32_t)__cvta_generic_to_shared(smh);

    const int b    = blockIdx.y;
    const int qt   = (int)gridDim.x - 1 - (int)blockIdx.x;  // big first (LPT)
    const int tid  = threadIdx.x;
    const int lane = tid & 31;
    const int wid  = tid >> 5;
    const int g    = lane >> 2;
    const int t    = lane & 3;
    const int m0   = wid * 16;
    const float scale2 = 0.08838834764831843f * 1.4426950408889634f;

    const int lrow = lane & 15;
    const int lcol = (lane >> 4) * 16;

    const __half* Kg = g_K + (size_t)b * T_ * H_;
    const __half* Vg = g_V + (size_t)b * T_ * H_;
    const __half* Qg = g_Q + ((size_t)b * T_ + (size_t)qt * 64) * H_;

    const int cr = tid >> 4;          // copy row
    const int cc = (tid & 15) * 8;    // copy col (halfs), 16B chunks

    // prologue: Q then K(0), each its own group
#pragma unroll
    for (int p = 0; p < 8; p++) {
        int r = cr + p * 8;
        CPA16(sm_u + SM_Q + (uint32_t)(r * KSTRH + cc) * 2, Qg + (size_t)r * H_ + cc);
    }
    CP_COMMIT();
#pragma unroll
    for (int p = 0; p < 8; p++) {
        int r = cr + p * 8;
        CPA16(sm_u + SM_K0 + (uint32_t)(r * KSTRH + cc) * 2, Kg + (size_t)r * H_ + cc);
    }
    CP_COMMIT();

    float of[16][4];
#pragma unroll
    for (int nf = 0; nf < 16; nf++)
#pragma unroll
        for (int e = 0; e < 4; e++) of[nf][e] = 0.f;
    float mrow[2] = {-1e30f, -1e30f};
    float lrow_[2] = {0.f, 0.f};

    const int nj = qt + 1;
    for (int j = 0; j < nj; j++) {
        // group A: V(j)
#pragma unroll
        for (int p = 0; p < 8; p++) {
            int r = cr + p * 8;
            CPA16(sm_u + SM_V + (uint32_t)(r * KSTRH + cc) * 2,
                  Vg + (size_t)(j * 64 + r) * H_ + cc);
        }
        CP_COMMIT();
        // group B: K(j+1) (or empty, to keep group arithmetic fixed)
        if (j + 1 < nj) {
            uint32_t kb = (j & 1) ? SM_K0 : SM_K1;
#pragma unroll
            for (int p = 0; p < 8; p++) {
                int r = cr + p * 8;
                CPA16(sm_u + kb + (uint32_t)(r * KSTRH + cc) * 2,
                      Kg + (size_t)((j + 1) * 64 + r) * H_ + cc);
            }
        }
        CP_COMMIT();

        CP_WAIT2();        // K(j) (and Q) complete
        __syncthreads();

        const uint32_t ks = sm_u + ((j & 1) ? SM_K1 : SM_K0);

        // ---- S = Q K^T : 16x64 per warp, 8 k-chunks of 16
        float s[8][4];
#pragma unroll
        for (int nf = 0; nf < 8; nf++)
#pragma unroll
            for (int e = 0; e < 4; e++) s[nf][e] = 0.f;

#pragma unroll
        for (int kc = 0; kc < 8; kc++) {
            uint32_t a0, a1, a2, a3;
            ldsm_x4(a0, a1, a2, a3,
                    sm_u + SM_Q + (uint32_t)((m0 + lrow) * KSTRH * 2 + kc * 32 + lcol));
#pragma unroll
            for (int r = 0; r < 4; r++) {
                uint32_t b00, b01, b10, b11;
                ldsm_x4(b00, b01, b10, b11,
                        ks + (uint32_t)((16 * r + lrow) * KSTRH * 2 + kc * 32 + lcol));
                mma_f16(s[2 * r], a0, a1, a2, a3, b00, b10);
                mma_f16(s[2 * r + 1], a0, a1, a2, a3, b01, b11);
            }
        }

        // ---- exp2 domain + causal mask (diagonal tile only)
#pragma unroll
        for (int nf = 0; nf < 8; nf++)
#pragma unroll
            for (int e = 0; e < 4; e++) s[nf][e] *= scale2;
        if (j == qt) {
            const int r0 = m0 + g, r1 = r0 + 8;
#pragma unroll
            for (int nf = 0; nf < 8; nf++) {
                int c0 = nf * 8 + 2 * t, c1 = c0 + 1;
                if (c0 > r0) s[nf][0] = -1e30f;
                if (c1 > r0) s[nf][1] = -1e30f;
                if (c0 > r1) s[nf][2] = -1e30f;
                if (c1 > r1) s[nf][3] = -1e30f;
            }
        }

        // ---- online softmax
        float mx0 = -1e30f, mx1 = -1e30f;
#pragma unroll
        for (int nf = 0; nf < 8; nf++) {
            mx0 = fmaxf(mx0, fmaxf(s[nf][0], s[nf][1]));
            mx1 = fmaxf(mx1, fmaxf(s[nf][2], s[nf][3]));
        }
        mx0 = fmaxf(mx0, __shfl_xor_sync(0xffffffffu, mx0, 1));
        mx0 = fmaxf(mx0, __shfl_xor_sync(0xffffffffu, mx0, 2));
        mx1 = fmaxf(mx1, __shfl_xor_sync(0xffffffffu, mx1, 1));
        mx1 = fmaxf(mx1, __shfl_xor_sync(0xffffffffu, mx1, 2));
        float mn0 = fmaxf(mrow[0], mx0), mn1 = fmaxf(mrow[1], mx1);
        float corr0 = fast_exp2(mrow[0] - mn0), corr1 = fast_exp2(mrow[1] - mn1);

        float rs0 = 0.f, rs1 = 0.f;
#pragma unroll
        for (int nf = 0; nf < 8; nf++) {
            s[nf][0] = fast_exp2(s[nf][0] - mn0);
            s[nf][1] = fast_exp2(s[nf][1] - mn0);
            s[nf][2] = fast_exp2(s[nf][2] - mn1);
            s[nf][3] = fast_exp2(s[nf][3] - mn1);
            rs0 += s[nf][0] + s[nf][1];
            rs1 += s[nf][2] + s[nf][3];
        }
        rs0 += __shfl_xor_sync(0xffffffffu, rs0, 1);
        rs0 += __shfl_xor_sync(0xffffffffu, rs0, 2);
        rs1 += __shfl_xor_sync(0xffffffffu, rs1, 1);
        rs1 += __shfl_xor_sync(0xffffffffu, rs1, 2);
        lrow_[0] = lrow_[0] * corr0 + rs0;
        lrow_[1] = lrow_[1] * corr1 + rs1;
        mrow[0] = mn0; mrow[1] = mn1;

#pragma unroll
        for (int nf = 0; nf < 16; nf++) {
            of[nf][0] *= corr0; of[nf][1] *= corr0;
            of[nf][2] *= corr1; of[nf][3] *= corr1;
        }

        // ---- pack P: C-frag pairs -> fp16 A-frag halves (FA2 identity)
        uint32_t p0[8], p1[8];
#pragma unroll
        for (int nf = 0; nf < 8; nf++) {
            p0[nf] = pack_h2(s[nf][0], s[nf][1]);
            p1[nf] = pack_h2(s[nf][2], s[nf][3]);
        }

        CP_WAIT1();        // V(j) complete
        __syncthreads();

        // ---- O += P V : 4 kv-chunks of 16, V via ldmatrix.trans
#pragma unroll
        for (int kc = 0; kc < 4; kc++) {
            uint32_t a0 = p0[2 * kc], a1 = p1[2 * kc];
            uint32_t a2 = p0[2 * kc + 1], a3 = p1[2 * kc + 1];
#pragma unroll
            for (int hp = 0; hp < 8; hp++) {
                uint32_t v0, v1, v2, v3;
                ldsm_x4_t(v0, v1, v2, v3,
                          sm_u + SM_V +
                          (uint32_t)((16 * kc + lrow) * KSTRH * 2 + hp * 32 + lcol));
                mma_f16(of[2 * hp], a0, a1, a2, a3, v0, v1);
                mma_f16(of[2 * hp + 1], a0, a1, a2, a3, v2, v3);
            }
        }
        __syncthreads();   // vbuf / kbuf free for next iteration's cp.async
    }

    // ---- epilogue
    float inv0 = 1.f / lrow_[0], inv1 = 1.f / lrow_[1];
    size_t orow = (size_t)b * T_ + (size_t)qt * 64 + m0 + g;
#pragma unroll
    for (int nf = 0; nf < 16; nf++) {
        int col = nf * 8 + 2 * t;
        *(float2*)&out[orow * H_ + col] =
            make_float2(of[nf][0] * inv0, of[nf][1] * inv0);
        *(float2*)&out[(orow + 8) * H_ + col] =
            make_float2(of[nf][2] * inv1, of[nf][3] * inv1);
    }
}

extern "C" void kernel_launch(void* const* d_in, const int* in_sizes, int n_in,
                              void* d_out, int out_size) {
    const float* x  = (const float*)d_in[0];
    const float* Wq = (const float*)d_in[1];
    const float* Wk = (const float*)d_in[2];
    const float* Wv = (const float*)d_in[3];
    float* out = (float*)d_out;

    qkv_tc_kernel<<<dim3(256, 3), 256>>>(x, Wq, Wk, Wv);

    cudaFuncSetAttribute(attn_tc_kernel,
                         cudaFuncAttributeMaxDynamicSharedMemorySize,
                         ATTN_SMEM_BYTES);
    attn_tc_kernel<<<dim3(T_ / 64, B_), 128, ATTN_SMEM_BYTES>>>(out);
}